// round 14
// baseline (speedup 1.0000x reference)
#include <cuda_runtime.h>

// HMM forward CgpHmmCell (nCodons=2): 24 states + 2 helper nodes, batch=2048, T=2000.
// R14: TWO sequences per warp, 16 lanes each; 26 nodes packed into 13 lanes
// (2 states/lane, pairs chosen to share gather sources). Per warp-step:
// 4 shfl + 1 LDS.64 serves BOTH sequences -> serial-chain cost halved per seq.

#define T_LEN 2000
#define BATCH 2048

__device__ int4   g_gidx[16];    // per-half-lane gather indices (A0,A1,B0,B1)
__device__ float4 g_ca4[16];     // coefs for state_a over (xA0,xA1,xB0,xB1)
__device__ float4 g_cb4[16];     // coefs for state_b
__device__ float4 g_cra4[16];    // raw coefs (t=1) for state_a
__device__ float4 g_crb4[16];    // raw coefs for state_b
__device__ float2 g_ds2[16];     // beta scale after t=1
__device__ float2 g_iv2[16];     // 1/scale for final correction
__device__ float2 g_pi2[16];     // initial pi per (lane, slot)
__device__ float2 g_E2[64 * 16]; // [ctx][hl] = (E_node_a, E_node_b)
__device__ unsigned short g_off[BATCH * T_LEN];

// ---------------------------------------------------------------------------
// Combined prep kernel: blocks 0..1999 ctx stream; block 2000 setup.
// ---------------------------------------------------------------------------
__device__ __forceinline__ float emisE(const float* __restrict__ ew, int node, int ctx) {
    if (node < 0) return 0.0f;
    int st = (node < 17) ? node : (node == 24) ? 10 : (node == 25) ? 7 : -2;
    if (st == -2) return 1.0f;           // non-emitting states 17..23
    int pq = ctx >> 2, c = ctx & 3;
    const float* p = ew + st * 64 + pq * 4;
    float e0 = __expf(p[0]), e1 = __expf(p[1]), e2 = __expf(p[2]), e3 = __expf(p[3]);
    float inv = __fdividef(1.0f, e0 + e1 + e2 + e3);
    float ec = (c == 0) ? e0 : (c == 1) ? e1 : (c == 2) ? e2 : e3;
    return ec * inv;
}

__global__ void prep_kernel(const int* __restrict__ seq,
                            const float* __restrict__ w,
                            const float* __restrict__ ew,
                            const float* __restrict__ ik) {
    if (blockIdx.x < 2000) {
        int tidg = blockIdx.x * blockDim.x + threadIdx.x;
        int b = tidg / 250;
        int c = tidg % 250;
        const int4* row = reinterpret_cast<const int4*>(seq + b * T_LEN);
        int i = c * 2;
        int4 a = row[i];
        int4 d = row[i + 1];
        int4 e = (i + 2 < 500) ? row[i + 2] : make_int4(0, 0, 0, 0);
        int s[12] = {a.x, a.y, a.z, a.w, d.x, d.y, d.z, d.w, e.x, e.y, e.z, e.w};
        unsigned short o[8];
        int p0 = c * 8;
        #pragma unroll
        for (int k = 0; k < 8; k++) {
            int ctx = (s[k] << 4) | (s[k + 1] << 2) | s[k + 2];
            o[k] = (p0 + k < 1998) ? (unsigned short)(ctx << 7) : (unsigned short)0;
        }
        reinterpret_cast<int4*>(g_off)[tidg] = *reinterpret_cast<int4*>(o);
        return;
    }

    // ---------------- setup block ----------------
    __shared__ float sv[17];
    __shared__ float spi[24];
    int tid = threadIdx.x;

    if (tid < 8) {
        float w12 = w[12];
        float d1 = 1.0f - w12 * w12;
        float d2 = 1.0f - w12 * w12 * w12;
        switch (tid) {
        case 0: {
            float e0 = __expf(1.0f - w[0]), e1 = __expf(w[0]);
            float inv = __fdividef(1.0f, e0 + e1);
            sv[0] = e0 * inv; sv[1] = e1 * inv;
        } break;
        case 1: {
            float e0 = __expf(w[1]), e1 = __expf(w[3]),
                  e2 = __expf(d1),  e3 = __expf(d2);
            float inv = __fdividef(1.0f, e0 + e1 + e2 + e3);
            sv[2] = e0 * inv; sv[3] = e1 * inv; sv[4] = e2 * inv; sv[5] = e3 * inv;
        } break;
        case 2: {
            float e0 = __expf(w[2]), e1 = __expf(w[4]), e2 = __expf(d1);
            float inv = __fdividef(1.0f, e0 + e1 + e2);
            sv[6] = e0 * inv; sv[7] = e1 * inv; sv[8] = e2 * inv;
        } break;
        case 3: {
            float e0 = __expf(w[5]), e1 = __expf(1.0f - w[5]);
            float inv = __fdividef(1.0f, e0 + e1);
            sv[9] = e0 * inv; sv[10] = e1 * inv;
        } break;
        case 4: {
            float e0 = __expf(w[6]), e1 = __expf(1.0f - w[9]);
            float inv = __fdividef(1.0f, e0 + e1);
            sv[11] = e0 * inv; sv[12] = e1 * inv;
        } break;
        case 5: {
            float e0 = __expf(w[7]), e1 = __expf(1.0f - w[10]);
            float inv = __fdividef(1.0f, e0 + e1);
            sv[13] = e0 * inv; sv[14] = e1 * inv;
        } break;
        case 6: {
            float e0 = __expf(w[8]), e1 = __expf(1.0f - w[11]);
            float inv = __fdividef(1.0f, e0 + e1);
            sv[15] = e0 * inv; sv[16] = e1 * inv;
        } break;
        case 7: {
            float e[24]; float s = 0.0f;
            #pragma unroll
            for (int i2 = 0; i2 < 24; i2++) { e[i2] = __expf(ik[i2]); s += e[i2]; }
            float inv = __fdividef(1.0f, s);
            #pragma unroll
            for (int i2 = 0; i2 < 24; i2++) spi[i2] = e[i2] * inv;
        } break;
        }
    }
    __syncthreads();

    if (tid == 0) {
        float a00 = sv[0],  a01   = sv[1];
        float a34 = sv[2],  a314  = sv[3],  a37 = sv[4], a310 = sv[5];
        float a67 = sv[6],  a617  = sv[7],  a610 = sv[8];
        float a920 = sv[9], a910  = sv[10];
        float a164 = sv[11], a1614 = sv[12];
        float a197 = sv[13], a1917 = sv[14];
        float a2210 = sv[15], a2220 = sv[16];
        const float S6 = 1.0f / 6.0f, S36 = 1.0f / 36.0f, S216 = 1.0f / 216.0f;

        // defaults
        for (int h = 0; h < 16; h++) {
            g_gidx[h] = make_int4(h, h, h, h);
            g_ca4[h]  = make_float4(0, 0, 0, 0);
            g_cb4[h]  = make_float4(0, 0, 0, 0);
            g_cra4[h] = make_float4(0, 0, 0, 0);
            g_crb4[h] = make_float4(0, 0, 0, 0);
            g_ds2[h]  = make_float2(1, 1);
            g_iv2[h]  = make_float2(1, 1);
            g_pi2[h]  = make_float2(0, 0);
        }
        // hl: (node_a, node_b); gathers (A0,A1,B0,B1) with A from slot-a regs, B slot-b.
        // hl0: (0,1) g A0=hl0(n0)
        g_gidx[0] = make_int4(0, 0, 0, 0);
        g_ca4[0]  = make_float4(a00, 0, 0, 0);  g_cb4[0]  = make_float4(a01, 0, 0, 0);
        // hl1: (2,3): A0=hl1(n2 self for state3), B0=hl0(n1 for state2)
        g_gidx[1] = make_int4(1, 1, 0, 1);
        g_ca4[1]  = make_float4(0, 0, 1, 0);    g_cb4[1]  = make_float4(1, 0, 0, 0);
        // hl2: (4,14): B0=hl1(n3), B1=hl8(n16)
        g_gidx[2] = make_int4(2, 2, 1, 8);
        g_ca4[2]  = make_float4(0, 0, a34, a164);
        g_cb4[2]  = make_float4(0, 0, a314, a1614);
        // hl3: (5,6): A0=hl2(n4), A1=hl3(n5 self)
        g_gidx[3] = make_int4(2, 3, 3, 3);
        g_ca4[3]  = make_float4(1, 0, 0, 0);    g_cb4[3]  = make_float4(0, 1, 0, 0);
        // hl4: (7,10): B0=hl1(n3), B1=hl3(n6)
        g_gidx[4] = make_int4(4, 4, 1, 3);
        g_ca4[4]  = make_float4(0, 0, a37, a67);
        g_cb4[4]  = make_float4(0, 0, a310, a610);
        // hl5: (8,9): A0=hl4(n7), A1=hl5(n8 self), B0=hl9(n25)
        g_gidx[5] = make_int4(4, 5, 9, 5);
        g_ca4[5]  = make_float4(1, 0, 1, 0);    g_cb4[5]  = make_float4(0, 1, 0, 0);
        // hl6: (11,12): A0=hl6(n11 self), B0=hl4(n10), B1=hl11(n24)
        g_gidx[6] = make_int4(6, 6, 4, 11);
        g_ca4[6]  = make_float4(0, 0, 1, 1);    g_cb4[6]  = make_float4(1, 0, 0, 0);
        // hl7: (13,23): A0=hl7(n13 self), B0=hl6(n12), B1=hl7(n23 self)
        g_gidx[7] = make_int4(7, 7, 6, 7);
        g_ca4[7]  = make_float4(0.5f, 0, 1, 0);
        g_cb4[7]  = make_float4(0.5f * S6, 0, 0, S6);
        // hl8: (15,16): A0=hl8(n15 self), B0=hl2(n14)
        g_gidx[8] = make_int4(8, 8, 2, 8);
        g_ca4[8]  = make_float4(0, 0, 1, 0);    g_cb4[8]  = make_float4(1, 0, 0, 0);
        // hl9: (17,25): B0=hl3(n6), B1=hl10(n19)
        g_gidx[9] = make_int4(9, 9, 3, 10);
        g_ca4[9]  = make_float4(0, 0, a617 * S6, a1917 * S216);
        g_cb4[9]  = make_float4(0, 0, 0, a197 * S36);
        // hl10: (18,19): A0=hl9(n17), A1=hl10(n18 self)
        g_gidx[10] = make_int4(9, 10, 10, 10);
        g_ca4[10]  = make_float4(1, 0, 0, 0);   g_cb4[10] = make_float4(0, 1, 0, 0);
        // hl11: (20,24): B0=hl5(n9), B1=hl12(n22)
        g_gidx[11] = make_int4(11, 11, 5, 12);
        g_ca4[11]  = make_float4(0, 0, a920 * S6, a2220 * S216);
        g_cb4[11]  = make_float4(0, 0, a910, a2210 * S36);
        // hl12: (21,22): A0=hl11(n20), A1=hl12(n21 self)
        g_gidx[12] = make_int4(11, 12, 12, 12);
        g_ca4[12]  = make_float4(1, 0, 0, 0);   g_cb4[12] = make_float4(0, 1, 0, 0);

        // raw coefs (t=1): same structure, unscaled values where scaling applied
        for (int h = 0; h < 13; h++) { g_cra4[h] = g_ca4[h]; g_crb4[h] = g_cb4[h]; }
        g_cra4[7]  = make_float4(0.5f, 0, 1, 0);
        g_crb4[7]  = make_float4(0.5f, 0, 0, 1);
        g_cra4[9]  = make_float4(0, 0, a617, a1917);
        g_crb4[9]  = make_float4(0, 0, 0, a197);
        g_cra4[11] = make_float4(0, 0, a920, a2220);
        g_crb4[11] = make_float4(0, 0, a910, a2210);

        // beta scales: nodes 18(hl10 a),19(hl10 b),21(hl12 a),22(hl12 b)
        g_ds2[10] = make_float2(6.0f, 36.0f);
        g_iv2[10] = make_float2(S6, S36);
        g_ds2[12] = make_float2(6.0f, 36.0f);
        g_iv2[12] = make_float2(S6, S36);

        // pi per (hl, slot); helper nodes 24,25 start at 0
        const int na[16] = {0,2,4,5,7,8,11,13,15,17,18,20,21,-1,-1,-1};
        const int nb[16] = {1,3,14,6,10,9,12,23,16,25,19,24,22,-1,-1,-1};
        for (int h = 0; h < 13; h++) {
            float pa = (na[h] >= 0 && na[h] < 24) ? spi[na[h]] : 0.0f;
            float pb = (nb[h] >= 0 && nb[h] < 24) ? spi[nb[h]] : 0.0f;
            g_pi2[h] = make_float2(pa, pb);
        }
    }
    __syncthreads();

    // E2 table: [ctx][hl] = (E(node_a), E(node_b)); helper nodes use parent E.
    {
        const int na[16] = {0,2,4,5,7,8,11,13,15,17,18,20,21,-1,-1,-1};
        const int nb[16] = {1,3,14,6,10,9,12,23,16,25,19,24,22,-1,-1,-1};
        for (int idx = tid; idx < 64 * 16; idx += blockDim.x) {
            int ctx = idx >> 4;
            int h   = idx & 15;
            g_E2[idx] = make_float2(emisE(ew, na[h], ctx), emisE(ew, nb[h], ctx));
        }
    }
}

// ---------------------------------------------------------------------------
// Forward kernel: one warp = two sequences (lanes 0-15 / 16-31).
// ---------------------------------------------------------------------------
__global__ __launch_bounds__(32)
void forward_kernel(float* __restrict__ out) {
    __shared__ __align__(16) float2 Tb[64 * 16];   // 8 KB
    {
        const float4* src = reinterpret_cast<const float4*>(g_E2);
        float4* dst = reinterpret_cast<float4*>(Tb);
        for (int i = threadIdx.x; i < 512; i += 32) dst[i] = src[i];
    }
    __syncwarp();

    const unsigned FULL = 0xffffffffu;
    const int lane = threadIdx.x & 31;
    const int hl   = lane & 15;
    const int hi   = lane & 16;
    const int wid  = blockIdx.x;
    const int seqid = wid + (hi ? 1024 : 0);

    int4 gi = g_gidx[hl];
    const int giA0 = gi.x | hi, giA1 = gi.y | hi, giB0 = gi.z | hi, giB1 = gi.w | hi;
    const float4 ca = g_ca4[hl];
    const float4 cb = g_cb4[hl];
    const float2 iv = g_iv2[hl];
    const char* tbB = reinterpret_cast<const char*>(Tb) + hl * 8;

    const uint4* offp = reinterpret_cast<const uint4*>(g_off + (size_t)seqid * T_LEN);

    float2 pi2 = g_pi2[hl];
    float bA = pi2.x, bB = pi2.y;

    // t=1 raw transition step, then beta scale
    {
        float4 ra = g_cra4[hl], rb = g_crb4[hl];
        float2 ds = g_ds2[hl];
        float xA0 = __shfl_sync(FULL, bA, giA0);
        float xA1 = __shfl_sync(FULL, bA, giA1);
        float xB0 = __shfl_sync(FULL, bB, giB0);
        float xB1 = __shfl_sync(FULL, bB, giB1);
        float ta = fmaf(ra.y, xA1, ra.x * xA0) + fmaf(ra.w, xB1, ra.z * xB0);
        float tb = fmaf(rb.y, xA1, rb.x * xA0) + fmaf(rb.w, xB1, rb.z * xB0);
        bA = ds.x * ta;
        bB = ds.y * tb;
    }

    float ll = -3.58351893845611f;   // 2 * ln(1/6)
    float pending_inv = 1.0f;

#define STEP(OFF) do { \
        float xA0 = __shfl_sync(FULL, bA, giA0); \
        float xA1 = __shfl_sync(FULL, bA, giA1); \
        float xB0 = __shfl_sync(FULL, bB, giB0); \
        float xB1 = __shfl_sync(FULL, bB, giB1); \
        float2 ev = *reinterpret_cast<const float2*>(tbB + (OFF)); \
        float ta = fmaf(ca.y, xA1, ca.x * xA0) + fmaf(ca.w, xB1, ca.z * xB0); \
        float tb = fmaf(cb.y, xA1, cb.x * xA0) + fmaf(cb.w, xB1, cb.z * xB0); \
        bA = ev.x * ta; \
        bB = ev.y * tb; \
    } while (0)

    uint4 c0 = offp[0];
    uint4 c1 = offp[1];
    #pragma unroll 2
    for (int j = 0; j < 249; ++j) {
        uint4 cn = offp[(j + 2 < 250) ? j + 2 : 249];
        unsigned o0 = c0.x & 0xffffu, o1 = c0.x >> 16;
        unsigned o2 = c0.y & 0xffffu, o3 = c0.y >> 16;
        unsigned o4 = c0.z & 0xffffu, o5 = c0.z >> 16;
        unsigned o6 = c0.w & 0xffffu, o7 = c0.w >> 16;
        STEP(o0); STEP(o1); STEP(o2); STEP(o3);
        STEP(o4); STEP(o5); STEP(o6); STEP(o7);
        if ((j & 1) == 1) {          // every 16 steps, delayed apply
            bA *= pending_inv;
            bB *= pending_inv;
            float t = bA + bB;       // butterfly within 16-lane group
            t += __shfl_xor_sync(FULL, t, 8);
            t += __shfl_xor_sync(FULL, t, 4);
            t += __shfl_xor_sync(FULL, t, 2);
            t += __shfl_xor_sync(FULL, t, 1);
            ll += __logf(t);
            pending_inv = __fdividef(1.0f, t);
        }
        c0 = c1; c1 = cn;
    }

    // Epilogue: 6 remaining steps
    {
        unsigned o0 = c0.x & 0xffffu, o1 = c0.x >> 16;
        unsigned o2 = c0.y & 0xffffu, o3 = c0.y >> 16;
        unsigned o4 = c0.z & 0xffffu, o5 = c0.z >> 16;
        STEP(o0); STEP(o1); STEP(o2); STEP(o3); STEP(o4); STEP(o5);
    }
#undef STEP

    // Final: apply pending factor, beta -> alpha mass correction
    {
        bA *= pending_inv;
        bB *= pending_inv;
        float t = fmaf(bA, iv.x, bB * iv.y);
        t += __shfl_xor_sync(FULL, t, 8);
        t += __shfl_xor_sync(FULL, t, 4);
        t += __shfl_xor_sync(FULL, t, 2);
        t += __shfl_xor_sync(FULL, t, 1);
        ll += __logf(t);
    }

    if (hl == 0) out[seqid] = ll;
}

// ---------------------------------------------------------------------------
// Launch
// ---------------------------------------------------------------------------
extern "C" void kernel_launch(void* const* d_in, const int* in_sizes, int n_in,
                              void* d_out, int out_size) {
    const float* transition_kernel = (const float*)d_in[0];
    const float* emission_kernel   = (const float*)d_in[1];
    const float* init_kernel       = (const float*)d_in[2];
    const int*   seq               = (const int*)d_in[3];
    float* out = (float*)d_out;

    prep_kernel<<<2001, 256>>>(seq, transition_kernel, emission_kernel, init_kernel);
    forward_kernel<<<BATCH / 2, 32>>>(out);
}

// round 15
// speedup vs baseline: 1.0950x; 1.0950x over previous
#include <cuda_runtime.h>

// HMM forward CgpHmmCell (nCodons=2): 24 states + 2 helper lanes, batch=2048, T=2000.
// One warp per sequence, one lane per state; <=2 sources/lane.
// R15: cross-lane exchange moved from SHFL (rt~2) to per-warp smem scratch
// (STS+2xLDS, rt 1 each): 4 MIO-cyc/step instead of 5. Offsets precomputed.

#define T_LEN 2000
#define BATCH 2048
#define WPB   2
#define BLOCK (WPB * 32)

__device__ int2   g_src[32];
__device__ float2 g_cp[32];
__device__ float2 g_cr[32];
__device__ float  g_dsc[32];
__device__ float  g_invd[32];
__device__ float  g_pi[24];
__device__ float  g_Etab[64 * 32];
__device__ unsigned short g_off[BATCH * T_LEN];

// ---------------------------------------------------------------------------
// Combined prep kernel (identical to R13)
// ---------------------------------------------------------------------------
__global__ void prep_kernel(const int* __restrict__ seq,
                            const float* __restrict__ w,
                            const float* __restrict__ ew,
                            const float* __restrict__ ik) {
    if (blockIdx.x < 2000) {
        int tidg = blockIdx.x * blockDim.x + threadIdx.x;
        int b = tidg / 250;
        int c = tidg % 250;
        const int4* row = reinterpret_cast<const int4*>(seq + b * T_LEN);
        int i = c * 2;
        int4 a = row[i];
        int4 d = row[i + 1];
        int4 e = (i + 2 < 500) ? row[i + 2] : make_int4(0, 0, 0, 0);
        int s[12] = {a.x, a.y, a.z, a.w, d.x, d.y, d.z, d.w, e.x, e.y, e.z, e.w};
        unsigned short o[8];
        int p0 = c * 8;
        #pragma unroll
        for (int k = 0; k < 8; k++) {
            int ctx = (s[k] << 4) | (s[k + 1] << 2) | s[k + 2];
            o[k] = (p0 + k < 1998) ? (unsigned short)(ctx << 7) : (unsigned short)0;
        }
        reinterpret_cast<int4*>(g_off)[tidg] = *reinterpret_cast<int4*>(o);
        return;
    }

    __shared__ float sv[17];
    int tid = threadIdx.x;

    if (tid < 8) {
        float w12 = w[12];
        float d1 = 1.0f - w12 * w12;
        float d2 = 1.0f - w12 * w12 * w12;
        switch (tid) {
        case 0: {
            float e0 = __expf(1.0f - w[0]), e1 = __expf(w[0]);
            float inv = __fdividef(1.0f, e0 + e1);
            sv[0] = e0 * inv; sv[1] = e1 * inv;
        } break;
        case 1: {
            float e0 = __expf(w[1]), e1 = __expf(w[3]),
                  e2 = __expf(d1),  e3 = __expf(d2);
            float inv = __fdividef(1.0f, e0 + e1 + e2 + e3);
            sv[2] = e0 * inv; sv[3] = e1 * inv; sv[4] = e2 * inv; sv[5] = e3 * inv;
        } break;
        case 2: {
            float e0 = __expf(w[2]), e1 = __expf(w[4]), e2 = __expf(d1);
            float inv = __fdividef(1.0f, e0 + e1 + e2);
            sv[6] = e0 * inv; sv[7] = e1 * inv; sv[8] = e2 * inv;
        } break;
        case 3: {
            float e0 = __expf(w[5]), e1 = __expf(1.0f - w[5]);
            float inv = __fdividef(1.0f, e0 + e1);
            sv[9] = e0 * inv; sv[10] = e1 * inv;
        } break;
        case 4: {
            float e0 = __expf(w[6]), e1 = __expf(1.0f - w[9]);
            float inv = __fdividef(1.0f, e0 + e1);
            sv[11] = e0 * inv; sv[12] = e1 * inv;
        } break;
        case 5: {
            float e0 = __expf(w[7]), e1 = __expf(1.0f - w[10]);
            float inv = __fdividef(1.0f, e0 + e1);
            sv[13] = e0 * inv; sv[14] = e1 * inv;
        } break;
        case 6: {
            float e0 = __expf(w[8]), e1 = __expf(1.0f - w[11]);
            float inv = __fdividef(1.0f, e0 + e1);
            sv[15] = e0 * inv; sv[16] = e1 * inv;
        } break;
        case 7: {
            float e[24]; float s = 0.0f;
            #pragma unroll
            for (int i2 = 0; i2 < 24; i2++) { e[i2] = __expf(ik[i2]); s += e[i2]; }
            float inv = __fdividef(1.0f, s);
            #pragma unroll
            for (int i2 = 0; i2 < 24; i2++) g_pi[i2] = e[i2] * inv;
        } break;
        }
    }
    __syncthreads();

    if (tid == 0) {
        float a00 = sv[0],  a01   = sv[1];
        float a34 = sv[2],  a314  = sv[3],  a37 = sv[4], a310 = sv[5];
        float a67 = sv[6],  a617  = sv[7],  a610 = sv[8];
        float a920 = sv[9], a910  = sv[10];
        float a164 = sv[11], a1614 = sv[12];
        float a197 = sv[13], a1917 = sv[14];
        float a2210 = sv[15], a2220 = sv[16];
        const float S6 = 1.0f / 6.0f, S36 = 1.0f / 36.0f, S216 = 1.0f / 216.0f;

        for (int l = 0; l < 32; l++) {
            g_src[l]  = make_int2(l, l);
            g_cp[l]   = make_float2(0.f, 0.f);
            g_cr[l]   = make_float2(0.f, 0.f);
            g_dsc[l]  = 1.0f;
            g_invd[l] = 1.0f;
        }
        g_src[0]  = make_int2(0, 0);   g_cp[0]  = make_float2(a00, 0);          g_cr[0]  = g_cp[0];
        g_src[1]  = make_int2(0, 1);   g_cp[1]  = make_float2(a01, 0);          g_cr[1]  = g_cp[1];
        g_src[2]  = make_int2(1, 2);   g_cp[2]  = make_float2(1, 0);            g_cr[2]  = g_cp[2];
        g_src[3]  = make_int2(2, 3);   g_cp[3]  = make_float2(1, 0);            g_cr[3]  = g_cp[3];
        g_src[4]  = make_int2(3, 16);  g_cp[4]  = make_float2(a34, a164);       g_cr[4]  = g_cp[4];
        g_src[5]  = make_int2(4, 5);   g_cp[5]  = make_float2(1, 0);            g_cr[5]  = g_cp[5];
        g_src[6]  = make_int2(5, 6);   g_cp[6]  = make_float2(1, 0);            g_cr[6]  = g_cp[6];
        g_src[7]  = make_int2(3, 6);   g_cp[7]  = make_float2(a37, a67);        g_cr[7]  = g_cp[7];
        g_src[8]  = make_int2(7, 25);  g_cp[8]  = make_float2(1, 1);            g_cr[8]  = g_cp[8];
        g_src[9]  = make_int2(8, 9);   g_cp[9]  = make_float2(1, 0);            g_cr[9]  = g_cp[9];
        g_src[10] = make_int2(3, 6);   g_cp[10] = make_float2(a310, a610);      g_cr[10] = g_cp[10];
        g_src[11] = make_int2(10, 24); g_cp[11] = make_float2(1, 1);            g_cr[11] = g_cp[11];
        g_src[12] = make_int2(11, 12); g_cp[12] = make_float2(1, 0);            g_cr[12] = g_cp[12];
        g_src[13] = make_int2(12, 13); g_cp[13] = make_float2(1, 0.5f);         g_cr[13] = g_cp[13];
        g_src[14] = make_int2(3, 16);  g_cp[14] = make_float2(a314, a1614);     g_cr[14] = g_cp[14];
        g_src[15] = make_int2(14, 15); g_cp[15] = make_float2(1, 0);            g_cr[15] = g_cp[15];
        g_src[16] = make_int2(15, 16); g_cp[16] = make_float2(1, 0);            g_cr[16] = g_cp[16];
        g_src[17] = make_int2(6, 19);  g_cp[17] = make_float2(a617 * S6, a1917 * S216);
                                       g_cr[17] = make_float2(a617, a1917);
        g_src[18] = make_int2(17, 18); g_cp[18] = make_float2(1, 0);            g_cr[18] = g_cp[18];
        g_src[19] = make_int2(18, 19); g_cp[19] = make_float2(1, 0);            g_cr[19] = g_cp[19];
        g_src[20] = make_int2(9, 22);  g_cp[20] = make_float2(a920 * S6, a2220 * S216);
                                       g_cr[20] = make_float2(a920, a2220);
        g_src[21] = make_int2(20, 21); g_cp[21] = make_float2(1, 0);            g_cr[21] = g_cp[21];
        g_src[22] = make_int2(21, 22); g_cp[22] = make_float2(1, 0);            g_cr[22] = g_cp[22];
        g_src[23] = make_int2(13, 23); g_cp[23] = make_float2(0.5f * S6, S6);
                                       g_cr[23] = make_float2(0.5f, 1.0f);
        g_src[24] = make_int2(9, 22);  g_cp[24] = make_float2(a910, a2210 * S36);
                                       g_cr[24] = make_float2(a910, a2210);
        g_src[25] = make_int2(19, 25); g_cp[25] = make_float2(a197 * S36, 0);
                                       g_cr[25] = make_float2(a197, 0);
        g_dsc[18] = 6.0f;  g_invd[18] = S6;
        g_dsc[19] = 36.0f; g_invd[19] = S36;
        g_dsc[21] = 6.0f;  g_invd[21] = S6;
        g_dsc[22] = 36.0f; g_invd[22] = S36;
    }

    for (int idx = tid; idx < 64 * 32; idx += blockDim.x) {
        int ctx = idx >> 5;
        int l   = idx & 31;
        int st  = (l < 17) ? l : (l == 24) ? 10 : (l == 25) ? 7 : -1;
        float val;
        if (st >= 0) {
            int pq = ctx >> 2;
            int c  = ctx & 3;
            const float* p = ew + st * 64 + pq * 4;
            float e0 = __expf(p[0]), e1 = __expf(p[1]),
                  e2 = __expf(p[2]), e3 = __expf(p[3]);
            float inv = __fdividef(1.0f, e0 + e1 + e2 + e3);
            float ec = (c == 0) ? e0 : (c == 1) ? e1 : (c == 2) ? e2 : e3;
            val = ec * inv;
        } else if (l < 24) {
            val = 1.0f;
        } else {
            val = 0.0f;
        }
        g_Etab[idx] = val;
    }
}

// ---------------------------------------------------------------------------
// Forward kernel: smem-scratch lane exchange (no SHFL in hot loop)
// ---------------------------------------------------------------------------
__global__ __launch_bounds__(BLOCK)
void forward_kernel(float* __restrict__ out) {
    __shared__ __align__(16) float Tb[64 * 32];        // 8 KB E table
    __shared__ __align__(16) float Scr[WPB][32];       // per-warp exchange scratch
    {
        const float4* src = reinterpret_cast<const float4*>(g_Etab);
        float4* dst = reinterpret_cast<float4*>(Tb);
        for (int i = threadIdx.x; i < 64 * 32 / 4; i += BLOCK) dst[i] = src[i];
    }
    __syncthreads();

    const unsigned FULL = 0xffffffffu;
    const int lane = threadIdx.x & 31;
    const int wrp  = threadIdx.x >> 5;
    const int wid  = blockIdx.x * WPB + wrp;

    const int2   si   = g_src[lane];
    const float2 cp   = g_cp[lane];
    const float  invd = g_invd[lane];
    const char*  tbB  = reinterpret_cast<const char*>(Tb) + lane * 4;

    const unsigned scrb  = (unsigned)__cvta_generic_to_shared(&Scr[wrp][0]);
    const unsigned sself = scrb + lane * 4;
    const unsigned sx0   = scrb + si.x * 4;
    const unsigned sx1   = scrb + si.y * 4;

    const uint4* offp = reinterpret_cast<const uint4*>(g_off + (size_t)wid * T_LEN);

    float beta = (lane < 24) ? g_pi[lane] : 0.0f;

    // t=1: raw-coef transition step (shfl; runs once), then beta scale.
    {
        const float2 cr  = g_cr[lane];
        const float  dsc = g_dsc[lane];
        float x0 = __shfl_sync(FULL, beta, si.x);
        float x1 = __shfl_sync(FULL, beta, si.y);
        beta = dsc * fmaf(cr.y, x1, cr.x * x0);
    }

    float ll = -3.58351893845611f;   // 2 * ln(1/6)
    float pending_inv = 1.0f;

    // Exchange via per-warp smem scratch. Warp is convergent throughout the
    // loop; per-warp shared-memory ops are processed in order by the MIO
    // queue, and the asm memory clobbers pin compiler ordering.
#define STEP(OFF) do { \
        float x0, x1; \
        asm volatile("st.shared.f32 [%0], %1;" :: "r"(sself), "f"(beta) : "memory"); \
        asm volatile("ld.shared.f32 %0, [%1];" : "=f"(x0) : "r"(sx0) : "memory"); \
        asm volatile("ld.shared.f32 %0, [%1];" : "=f"(x1) : "r"(sx1) : "memory"); \
        float ev = *reinterpret_cast<const float*>(tbB + (OFF)); \
        beta = ev * fmaf(cp.y, x1, cp.x * x0); \
    } while (0)

    uint4 c0 = offp[0];
    uint4 c1 = offp[1];
    #pragma unroll 2
    for (int j = 0; j < 249; ++j) {
        uint4 cn = offp[(j + 2 < 250) ? j + 2 : 249];
        unsigned o0 = c0.x & 0xffffu, o1 = c0.x >> 16;
        unsigned o2 = c0.y & 0xffffu, o3 = c0.y >> 16;
        unsigned o4 = c0.z & 0xffffu, o5 = c0.z >> 16;
        unsigned o6 = c0.w & 0xffffu, o7 = c0.w >> 16;
        STEP(o0); STEP(o1); STEP(o2); STEP(o3);
        STEP(o4); STEP(o5); STEP(o6); STEP(o7);
        if ((j & 1) == 1) {          // every 16 steps, delayed apply
            beta *= pending_inv;
            float t = beta;
            t += __shfl_xor_sync(FULL, t, 16);
            t += __shfl_xor_sync(FULL, t, 8);
            t += __shfl_xor_sync(FULL, t, 4);
            t += __shfl_xor_sync(FULL, t, 2);
            t += __shfl_xor_sync(FULL, t, 1);
            ll += __logf(t);
            pending_inv = __fdividef(1.0f, t);
        }
        c0 = c1; c1 = cn;
    }

    // Epilogue: 6 remaining steps.
    {
        unsigned o0 = c0.x & 0xffffu, o1 = c0.x >> 16;
        unsigned o2 = c0.y & 0xffffu, o3 = c0.y >> 16;
        unsigned o4 = c0.z & 0xffffu, o5 = c0.z >> 16;
        STEP(o0); STEP(o1); STEP(o2); STEP(o3); STEP(o4); STEP(o5);
    }
#undef STEP

    // Final: apply pending factor, beta -> alpha mass correction.
    {
        beta *= pending_inv;
        float t = beta * invd;
        t += __shfl_xor_sync(FULL, t, 16);
        t += __shfl_xor_sync(FULL, t, 8);
        t += __shfl_xor_sync(FULL, t, 4);
        t += __shfl_xor_sync(FULL, t, 2);
        t += __shfl_xor_sync(FULL, t, 1);
        ll += __logf(t);
    }

    if (lane == 0) out[wid] = ll;
}

// ---------------------------------------------------------------------------
// Launch
// ---------------------------------------------------------------------------
extern "C" void kernel_launch(void* const* d_in, const int* in_sizes, int n_in,
                              void* d_out, int out_size) {
    const float* transition_kernel = (const float*)d_in[0];
    const float* emission_kernel   = (const float*)d_in[1];
    const float* init_kernel       = (const float*)d_in[2];
    const int*   seq               = (const int*)d_in[3];
    float* out = (float*)d_out;

    prep_kernel<<<2001, 256>>>(seq, transition_kernel, emission_kernel, init_kernel);
    forward_kernel<<<BATCH / WPB, BLOCK>>>(out);
}